// round 14
// baseline (speedup 1.0000x reference)
#include <cuda_runtime.h>
#include <cuda_fp16.h>
#include <math.h>

#define NN_MAX 100000
#define NE_MAX 1600000
#define FG 128
#define FIN 512
#define GMAX 512
#define ZD 64
#define HID 64
#define SCAN_BLK 512
#define MAX_NB 256
#define NODES_PER_WARP 4

// ---------------- scratch (device globals) ----------------
__device__ __half g_xh [NN_MAX * FG];   // (x @ Wg) * dinv[row], fp16 gather payload
__device__ float g_dinv[NN_MAX];        // 1/sqrt(deg)
__device__ int   g_icnt[NN_MAX];        // in-degree (excl self loop)
__device__ int   g_rowptr[NN_MAX];      // CSR row starts
__device__ int   g_cur [NN_MAX];        // fill cursors
__device__ int   g_csr [NE_MAX];        // src node per CSR slot
__device__ int   g_bsum[MAX_NB];        // scan block sums (RAW totals, not scanned)
__device__ unsigned g_wtf[FIN * FG];    // Wg pre-converted to tf32 bits
__device__ float g_psum[GMAX * FG];     // pool sum
__device__ unsigned g_pmax[GMAX * FG];  // pool max (float bits, vals >= 0)
__device__ float g_cnt [GMAX];          // nodes per graph

__device__ __forceinline__ unsigned f2tf32(float v) {
    unsigned r;
    asm("cvt.rna.tf32.f32 %0, %1;" : "=r"(r) : "f"(v));
    return r;
}

// ---------------- fused pre-kernel: pool init + icnt zero + W tf32 convert ----------------
__global__ void k_pre(const float* __restrict__ W, int N) {
    int i = blockIdx.x * blockDim.x + threadIdx.x;
    if (i < GMAX * FG) { g_psum[i] = 0.f; g_pmax[i] = 0u; }
    if (i < GMAX) g_cnt[i] = 0.f;
    if (i < N) g_icnt[i] = 0;
    if (i < FIN * FG / 4) {
        float4 v = *(const float4*)&W[i * 4];
        uint4 u;
        u.x = f2tf32(v.x); u.y = f2tf32(v.y);
        u.z = f2tf32(v.z); u.w = f2tf32(v.w);
        *(uint4*)&g_wtf[i * 4] = u;
    }
}

// ---------------- degree histogram ----------------
__global__ void k_deg(const int* __restrict__ dst, int E) {
    int e = blockIdx.x * blockDim.x + threadIdx.x;
    if (e < E) atomicAdd(&g_icnt[dst[e]], 1);
}

// ---------------- per-chunk scan of icnt -> local rowptr + chunk totals ----------------
__global__ void k_scan1(int N) {
    __shared__ int sh[SCAN_BLK];
    int tid = threadIdx.x;
    int i = blockIdx.x * SCAN_BLK + tid;
    int v = (i < N) ? g_icnt[i] : 0;
    sh[tid] = v;
    __syncthreads();
#pragma unroll
    for (int off = 1; off < SCAN_BLK; off <<= 1) {
        int t = (tid >= off) ? sh[tid - off] : 0;
        __syncthreads();
        sh[tid] += t;
        __syncthreads();
    }
    if (i < N) g_rowptr[i] = sh[tid] - v;                 // exclusive within chunk
    if (tid == SCAN_BLK - 1) g_bsum[blockIdx.x] = sh[tid]; // chunk TOTAL (raw)
}

// fixup: each block reduces g_bsum[0..chunk) itself (chunk = blockIdx>>1), + cursor + dinv
__global__ void k_scan3(int N) {
    __shared__ int red[256];
    int tid = threadIdx.x;
    int i = blockIdx.x * 256 + tid;
    int chunk = blockIdx.x >> 1;     // 256-thread block spans exactly one 512-chunk

    int v = (tid < chunk) ? g_bsum[tid] : 0;   // chunk <= 195 < 256
    red[tid] = v;
    __syncthreads();
#pragma unroll
    for (int off = 128; off > 0; off >>= 1) {
        if (tid < off) red[tid] += red[tid + off];
        __syncthreads();
    }
    int prefix = red[0];

    if (i < N) {
        int r = g_rowptr[i] + prefix;
        g_rowptr[i] = r;
        g_cur[i] = r;
        g_dinv[i] = rsqrtf((float)(g_icnt[i] + 1));   // +1 self loop
    }
}

// ---------------- CSR fill ----------------
__global__ void k_fill(const int* __restrict__ src, const int* __restrict__ dst, int E) {
    int e = blockIdx.x * blockDim.x + threadIdx.x;
    if (e < E) {
        int pos = atomicAdd(&g_cur[dst[e]], 1);
        g_csr[pos] = src[e];
    }
}

// ---------------- TF32 GEMM, cp.async 3-stage, conflict-free B stride ----------------
#define BM 128
#define BN 128
#define BK 32
#define TILES (FIN / BK)
#define STAGES 3
#define ASTRIDE 36    // bank = 4g + tig : 32 distinct (A frag loads conflict-free)
#define BSTRIDE 136   // 136 % 32 == 8 -> bank = 8*tig + g : 32 distinct (was 2-way @132)

__global__ __launch_bounds__(256, 2)
void k_gemm_tf32(const float* __restrict__ X, int M) {
    __shared__ float    As[STAGES][BM * ASTRIDE];
    __shared__ unsigned Bs[STAGES][BK * BSTRIDE];
    int tid = threadIdx.x;
    int lane = tid & 31, wid = tid >> 5;
    int warp_m = (wid & 3) * 32;
    int warp_n = (wid >> 2) * 64;
    int g  = lane >> 2;
    int tig = lane & 3;
    int block_row = blockIdx.x * BM;

    float acc[2][8][4];
#pragma unroll
    for (int m = 0; m < 2; m++)
#pragma unroll
        for (int n = 0; n < 8; n++)
#pragma unroll
            for (int c = 0; c < 4; c++) acc[m][n][c] = 0.f;

    auto load_tile = [&](int t, int b) {
        int k0 = t * BK;
#pragma unroll
        for (int i = 0; i < 4; i++) {
            int idx = tid + i * 256;
            int row = idx >> 3;
            int col = (idx & 7) * 4;
            int grow = block_row + row;
            int cg = grow < M ? grow : 0;
            int sz = grow < M ? 16 : 0;
            const float* src = &X[(size_t)cg * FIN + k0 + col];
            unsigned d = (unsigned)__cvta_generic_to_shared(&As[b][row * ASTRIDE + col]);
            asm volatile("cp.async.cg.shared.global [%0], [%1], 16, %2;"
                         :: "r"(d), "l"(src), "r"(sz));
        }
#pragma unroll
        for (int i = 0; i < 4; i++) {
            int idx = tid + i * 256;
            int kr = idx >> 5;
            int c4 = (idx & 31) * 4;
            const unsigned* src = &g_wtf[(size_t)(k0 + kr) * FG + c4];
            unsigned d = (unsigned)__cvta_generic_to_shared(&Bs[b][kr * BSTRIDE + c4]);
            asm volatile("cp.async.cg.shared.global [%0], [%1], 16;"
                         :: "r"(d), "l"(src));
        }
        asm volatile("cp.async.commit_group;");
    };

    load_tile(0, 0);
    load_tile(1, 1);

    for (int t = 0; t < TILES; t++) {
        if (t + 1 < TILES) {
            asm volatile("cp.async.wait_group %0;" :: "n"(1));
        } else {
            asm volatile("cp.async.wait_group %0;" :: "n"(0));
        }
        __syncthreads();
        if (t + 2 < TILES) load_tile(t + 2, (t + 2) % STAGES);

        int buf = t % STAGES;
#pragma unroll
        for (int kk = 0; kk < BK; kk += 8) {
            unsigned a[2][4];
#pragma unroll
            for (int m = 0; m < 2; m++) {
                int r0 = warp_m + m * 16 + g;
                a[m][0] = f2tf32(As[buf][(r0    ) * ASTRIDE + kk + tig]);
                a[m][1] = f2tf32(As[buf][(r0 + 8) * ASTRIDE + kk + tig]);
                a[m][2] = f2tf32(As[buf][(r0    ) * ASTRIDE + kk + tig + 4]);
                a[m][3] = f2tf32(As[buf][(r0 + 8) * ASTRIDE + kk + tig + 4]);
            }
            unsigned b[8][2];
#pragma unroll
            for (int n = 0; n < 8; n++) {
                int c0 = warp_n + n * 8 + g;
                b[n][0] = Bs[buf][(kk + tig    ) * BSTRIDE + c0];
                b[n][1] = Bs[buf][(kk + tig + 4) * BSTRIDE + c0];
            }
#pragma unroll
            for (int m = 0; m < 2; m++)
#pragma unroll
                for (int n = 0; n < 8; n++) {
                    asm volatile(
                        "mma.sync.aligned.m16n8k8.row.col.f32.tf32.tf32.f32 "
                        "{%0,%1,%2,%3}, {%4,%5,%6,%7}, {%8,%9}, {%0,%1,%2,%3};"
                        : "+f"(acc[m][n][0]), "+f"(acc[m][n][1]),
                          "+f"(acc[m][n][2]), "+f"(acc[m][n][3])
                        : "r"(a[m][0]), "r"(a[m][1]), "r"(a[m][2]), "r"(a[m][3]),
                          "r"(b[n][0]), "r"(b[n][1]));
                }
        }
    }

    // epilogue: scale by dinv[row], fp16 store
#pragma unroll
    for (int m = 0; m < 2; m++) {
        int r0 = block_row + warp_m + m * 16 + g;
        int r1 = r0 + 8;
        float d0 = (r0 < M) ? g_dinv[r0] : 0.f;
        float d1 = (r1 < M) ? g_dinv[r1] : 0.f;
#pragma unroll
        for (int n = 0; n < 8; n++) {
            int col = warp_n + n * 8 + tig * 2;
            if (r0 < M) {
                __half2 h = __floats2half2_rn(acc[m][n][0] * d0, acc[m][n][1] * d0);
                *(__half2*)&g_xh[(size_t)r0 * FG + col] = h;
            }
            if (r1 < M) {
                __half2 h = __floats2half2_rn(acc[m][n][2] * d1, acc[m][n][3] * d1);
                *(__half2*)&g_xh[(size_t)r1 * FG + col] = h;
            }
        }
    }
}

// ---- fp16 row load: 4 features per lane ----
__device__ __forceinline__ float4 ldrow4(size_t node, int c4) {
    uint2 u = *(const uint2*)&g_xh[node * FG + c4];
    float2 fa = __half22float2(*(__half2*)&u.x);
    float2 fb = __half22float2(*(__half2*)&u.y);
    return make_float4(fa.x, fa.y, fb.x, fb.y);
}

// ---- gather + pooling with register-resident segmented reduction ----
__device__ __forceinline__ void pool_flush(int b, int c4, float4 sum, float4 mx, int nodes) {
    float* ps = &g_psum[b * FG + c4];
    asm volatile("red.global.add.v4.f32 [%0], {%1,%2,%3,%4};"
                 :: "l"(ps), "f"(sum.x), "f"(sum.y), "f"(sum.z), "f"(sum.w) : "memory");
    int* pm = (int*)&g_pmax[b * FG + c4];
    atomicMax(pm + 0, __float_as_int(mx.x));
    atomicMax(pm + 1, __float_as_int(mx.y));
    atomicMax(pm + 2, __float_as_int(mx.z));
    atomicMax(pm + 3, __float_as_int(mx.w));
    if ((threadIdx.x & 31) == 0) atomicAdd(&g_cnt[b], (float)nodes);
}

__global__ void k_gather_pool(const int* __restrict__ batch, const float* __restrict__ bg, int N) {
    int warp = (blockIdx.x * blockDim.x + threadIdx.x) >> 5;
    int lane = threadIdx.x & 31;
    int n0 = warp * NODES_PER_WARP;
    if (n0 >= N) return;
    int n1 = n0 + NODES_PER_WARP; if (n1 > N) n1 = N;
    int c4 = lane * 4;
    float4 bv = *(const float4*)&bg[c4];

    float4 sum = make_float4(0.f, 0.f, 0.f, 0.f);
    float4 mx  = make_float4(0.f, 0.f, 0.f, 0.f);
    int cur_b = batch[n0];
    int nodes = 0;

    for (int n = n0; n < n1; n++) {
        int b = batch[n];
        if (b != cur_b) {
            pool_flush(cur_b, c4, sum, mx, nodes);
            sum = make_float4(0.f, 0.f, 0.f, 0.f);
            mx  = make_float4(0.f, 0.f, 0.f, 0.f);
            cur_b = b; nodes = 0;
        }
        float4 acc = ldrow4((size_t)n, c4);     // self-loop term (pre-scaled)
        int start = g_rowptr[n];
        int cnt   = g_icnt[n];
        int e = 0;
        for (; e + 4 <= cnt; e += 4) {
            int s0 = g_csr[start + e    ];
            int s1 = g_csr[start + e + 1];
            int s2 = g_csr[start + e + 2];
            int s3 = g_csr[start + e + 3];
            float4 v0 = ldrow4((size_t)s0, c4);
            float4 v1 = ldrow4((size_t)s1, c4);
            float4 v2 = ldrow4((size_t)s2, c4);
            float4 v3 = ldrow4((size_t)s3, c4);
            acc.x += v0.x + v1.x + v2.x + v3.x;
            acc.y += v0.y + v1.y + v2.y + v3.y;
            acc.z += v0.z + v1.z + v2.z + v3.z;
            acc.w += v0.w + v1.w + v2.w + v3.w;
        }
        for (; e < cnt; e++) {
            float4 v = ldrow4((size_t)g_csr[start + e], c4);
            acc.x += v.x; acc.y += v.y; acc.z += v.z; acc.w += v.w;
        }
        float di = g_dinv[n];
        float v0 = fmaxf(fmaf(acc.x, di, bv.x), 0.f);
        float v1 = fmaxf(fmaf(acc.y, di, bv.y), 0.f);
        float v2 = fmaxf(fmaf(acc.z, di, bv.z), 0.f);
        float v3 = fmaxf(fmaf(acc.w, di, bv.w), 0.f);
        sum.x += v0; sum.y += v1; sum.z += v2; sum.w += v3;
        mx.x = fmaxf(mx.x, v0); mx.y = fmaxf(mx.y, v1);
        mx.z = fmaxf(mx.z, v2); mx.w = fmaxf(mx.w, v3);
        nodes++;
    }
    pool_flush(cur_b, c4, sum, mx, nodes);
}

// ---------------- head: encoder/decoder MLPs ----------------
__device__ __forceinline__ float eluf(float x)      { return x > 0.f ? x : expm1f(x); }
__device__ __forceinline__ float softplusf(float x) { return x > 20.f ? x : log1pf(expf(x)); }

__global__ void k_head(const float* __restrict__ eps,
                       const float* __restrict__ We1, const float* __restrict__ be1,
                       const float* __restrict__ We2, const float* __restrict__ be2,
                       const float* __restrict__ We3, const float* __restrict__ be3,
                       const float* __restrict__ Wd1, const float* __restrict__ bd1,
                       const float* __restrict__ Wd2, const float* __restrict__ bd2,
                       const float* __restrict__ Wd3, const float* __restrict__ bd3,
                       float* __restrict__ out, int G) {
    __shared__ float gx[2 * FG];
    __shared__ float t1[HID], t2[HID], ml[2 * ZD], zz[ZD], dd1[HID], dd2[HID];
    int g = blockIdx.x;
    int tid = threadIdx.x;

    float cnt = fmaxf(g_cnt[g], 1.0f);
    gx[tid]      = g_psum[g * FG + tid] / cnt;
    gx[FG + tid] = __int_as_float(g_pmax[g * FG + tid]);
    __syncthreads();

    if (tid < HID) {
        float s = be1[tid];
#pragma unroll 8
        for (int i = 0; i < 2 * FG; i++) s = fmaf(gx[i], We1[i * HID + tid], s);
        t1[tid] = eluf(s);
    }
    __syncthreads();
    if (tid < HID) {
        float s = be2[tid];
#pragma unroll 8
        for (int i = 0; i < HID; i++) s = fmaf(t1[i], We2[i * HID + tid], s);
        t2[tid] = tanhf(s);
    }
    __syncthreads();
    {
        float s = be3[tid];
#pragma unroll 8
        for (int i = 0; i < HID; i++) s = fmaf(t2[i], We3[i * 2 * ZD + tid], s);
        ml[tid] = s;
    }
    __syncthreads();
    if (tid < ZD) {
        float mu = ml[tid];
        float sd = 1e-6f + softplusf(ml[ZD + tid]);
        float z = fmaf(eps[g * ZD + tid], sd, mu);
        zz[tid] = z;
        out[g * ZD + tid] = mu;
        out[G * ZD + g * ZD + tid] = sd;
    }
    __syncthreads();
    if (tid < HID) {
        float s = bd1[tid];
#pragma unroll 8
        for (int i = 0; i < ZD; i++) s = fmaf(zz[i], Wd1[i * HID + tid], s);
        dd1[tid] = tanhf(s);
    }
    __syncthreads();
    if (tid < HID) {
        float s = bd2[tid];
#pragma unroll 8
        for (int i = 0; i < HID; i++) s = fmaf(dd1[i], Wd2[i * HID + tid], s);
        dd2[tid] = eluf(s);
    }
    __syncthreads();
    {
        float s = bd3[tid];
#pragma unroll 8
        for (int i = 0; i < HID; i++) s = fmaf(dd2[i], Wd3[i * FG + tid], s);
        float y = 1.0f / (1.0f + expf(-s));
        y = fminf(fmaxf(y, 1e-8f), 1.0f - 1e-8f);
        out[2 * G * ZD + g * FG + tid] = y;
    }
}

// ---------------- launch (single stream, serial) ----------------
extern "C" void kernel_launch(void* const* d_in, const int* in_sizes, int n_in,
                              void* d_out, int out_size) {
    const float* x     = (const float*)d_in[0];
    const int*   ei    = (const int*)  d_in[1];
    const int*   batch = (const int*)  d_in[2];
    const float* eps   = (const float*)d_in[3];
    const float* Wg    = (const float*)d_in[4];
    const float* bg    = (const float*)d_in[5];
    const float* We1 = (const float*)d_in[6],  *be1 = (const float*)d_in[7];
    const float* We2 = (const float*)d_in[8],  *be2 = (const float*)d_in[9];
    const float* We3 = (const float*)d_in[10], *be3 = (const float*)d_in[11];
    const float* Wd1 = (const float*)d_in[12], *bd1 = (const float*)d_in[13];
    const float* Wd2 = (const float*)d_in[14], *bd2 = (const float*)d_in[15];
    const float* Wd3 = (const float*)d_in[16], *bd3 = (const float*)d_in[17];
    float* out = (float*)d_out;

    int N = in_sizes[0] / FIN;       // 100000
    int E = in_sizes[1] / 2;         // 1600000
    int G = in_sizes[3] / ZD;        // 512
    const int* src = ei;
    const int* dst = ei + E;
    int nb = (N + SCAN_BLK - 1) / SCAN_BLK;

    int pre_n = N > GMAX * FG ? N : GMAX * FG;
    k_pre<<<(pre_n + 255) / 256, 256>>>(Wg, N);
    k_deg<<<(E + 255) / 256, 256>>>(dst, E);
    k_scan1<<<nb, SCAN_BLK>>>(N);
    k_scan3<<<(N + 255) / 256, 256>>>(N);   // fused: bsum prefix + fixup + cursor + dinv
    k_fill<<<(E + 255) / 256, 256>>>(src, dst, E);
    k_gemm_tf32<<<(N + BM - 1) / BM, 256>>>(x, N);
    {
        int nwarps = (N + NODES_PER_WARP - 1) / NODES_PER_WARP;
        long long nthreads = (long long)nwarps * 32;
        k_gather_pool<<<(int)((nthreads + 255) / 256), 256>>>(batch, bg, N);
    }
    k_head<<<G, 128>>>(eps, We1, be1, We2, be2, We3, be3,
                       Wd1, bd1, Wd2, bd2, Wd3, bd3, out, G);
}

// round 15
// speedup vs baseline: 1.3561x; 1.3561x over previous
#include <cuda_runtime.h>
#include <cuda_fp16.h>
#include <math.h>

#define NN_MAX 100000
#define NE_MAX 1600000
#define FG 128
#define FIN 512
#define GMAX 512
#define ZD 64
#define HID 64
#define SCAN_BLK 512
#define MAX_NB 256
#define NODES_PER_WARP 8

// ---------------- scratch (device globals) ----------------
__device__ __half g_xh [NN_MAX * FG];   // (x @ Wg) * dinv[row], fp16 gather payload
__device__ float g_dinv[NN_MAX];        // 1/sqrt(deg)
__device__ int   g_icnt[NN_MAX];        // in-degree (excl self loop)
__device__ int   g_rowptr[NN_MAX];      // CSR row starts
__device__ int   g_cur [NN_MAX];        // fill cursors
__device__ int   g_csr [NE_MAX];        // src node per CSR slot
__device__ int   g_bsum[MAX_NB];        // scan block sums
__device__ unsigned g_wtf[FIN * FG];    // Wg pre-converted to tf32 bits
__device__ float g_psum[GMAX * FG];     // pool sum
__device__ unsigned g_pmax[GMAX * FG];  // pool max (float bits, vals >= 0)
__device__ float g_cnt [GMAX];          // nodes per graph

__device__ __forceinline__ unsigned f2tf32(float v) {
    unsigned r;
    asm("cvt.rna.tf32.f32 %0, %1;" : "=r"(r) : "f"(v));
    return r;
}

// ---------------- fused pre-kernel: pool init + icnt zero + W tf32 convert ----------------
__global__ void k_pre(const float* __restrict__ W, int N) {
    int i = blockIdx.x * blockDim.x + threadIdx.x;
    if (i < GMAX * FG) { g_psum[i] = 0.f; g_pmax[i] = 0u; }
    if (i < GMAX) g_cnt[i] = 0.f;
    if (i < N) g_icnt[i] = 0;
    if (i < FIN * FG / 4) {
        float4 v = *(const float4*)&W[i * 4];
        uint4 u;
        u.x = f2tf32(v.x); u.y = f2tf32(v.y);
        u.z = f2tf32(v.z); u.w = f2tf32(v.w);
        *(uint4*)&g_wtf[i * 4] = u;
    }
}

// ---------------- degree histogram ----------------
__global__ void k_deg(const int* __restrict__ dst, int E) {
    int e = blockIdx.x * blockDim.x + threadIdx.x;
    if (e < E) atomicAdd(&g_icnt[dst[e]], 1);
}

// ---------------- exclusive scan of icnt -> rowptr ----------------
__global__ void k_scan1(int N) {
    __shared__ int sh[SCAN_BLK];
    int tid = threadIdx.x;
    int i = blockIdx.x * SCAN_BLK + tid;
    int v = (i < N) ? g_icnt[i] : 0;
    sh[tid] = v;
    __syncthreads();
#pragma unroll
    for (int off = 1; off < SCAN_BLK; off <<= 1) {
        int t = (tid >= off) ? sh[tid - off] : 0;
        __syncthreads();
        sh[tid] += t;
        __syncthreads();
    }
    if (i < N) g_rowptr[i] = sh[tid] - v;
    if (tid == SCAN_BLK - 1) g_bsum[blockIdx.x] = sh[tid];
}

__global__ void k_scan2(int nb) {
    __shared__ int sh[MAX_NB];
    int tid = threadIdx.x;
    int v = (tid < nb) ? g_bsum[tid] : 0;
    sh[tid] = v;
    __syncthreads();
#pragma unroll
    for (int off = 1; off < MAX_NB; off <<= 1) {
        int t = (tid >= off) ? sh[tid - off] : 0;
        __syncthreads();
        sh[tid] += t;
        __syncthreads();
    }
    if (tid < nb) g_bsum[tid] = sh[tid] - v;
}

// scan fixup + cursor seed + dinv (fused)
__global__ void k_scan3(int N) {
    int i = blockIdx.x * blockDim.x + threadIdx.x;
    if (i < N) {
        int r = g_rowptr[i] + g_bsum[i / SCAN_BLK];
        g_rowptr[i] = r;
        g_cur[i] = r;
        g_dinv[i] = rsqrtf((float)(g_icnt[i] + 1));   // +1 self loop
    }
}

// ---------------- CSR fill ----------------
__global__ void k_fill(const int* __restrict__ src, const int* __restrict__ dst, int E) {
    int e = blockIdx.x * blockDim.x + threadIdx.x;
    if (e < E) {
        int pos = atomicAdd(&g_cur[dst[e]], 1);
        g_csr[pos] = src[e];
    }
}

// ---------------- TF32 GEMM, cp.async 3-stage, single barrier, conflict-free B stride ----------------
#define BM 128
#define BN 128
#define BK 32
#define TILES (FIN / BK)
#define STAGES 3
#define ASTRIDE 36    // A frag loads: bank = 4g + tig -> 32 distinct
#define BSTRIDE 136   // 136 % 32 == 8 -> bank = 8*tig + g -> 32 distinct (132 was 2-way)

__global__ __launch_bounds__(256, 2)
void k_gemm_tf32(const float* __restrict__ X, int M) {
    __shared__ float    As[STAGES][BM * ASTRIDE];
    __shared__ unsigned Bs[STAGES][BK * BSTRIDE];
    int tid = threadIdx.x;
    int lane = tid & 31, wid = tid >> 5;
    int warp_m = (wid & 3) * 32;
    int warp_n = (wid >> 2) * 64;
    int g  = lane >> 2;
    int tig = lane & 3;
    int block_row = blockIdx.x * BM;

    float acc[2][8][4];
#pragma unroll
    for (int m = 0; m < 2; m++)
#pragma unroll
        for (int n = 0; n < 8; n++)
#pragma unroll
            for (int c = 0; c < 4; c++) acc[m][n][c] = 0.f;

    auto load_tile = [&](int t, int b) {
        int k0 = t * BK;
#pragma unroll
        for (int i = 0; i < 4; i++) {
            int idx = tid + i * 256;
            int row = idx >> 3;
            int col = (idx & 7) * 4;
            int grow = block_row + row;
            int cg = grow < M ? grow : 0;
            int sz = grow < M ? 16 : 0;
            const float* src = &X[(size_t)cg * FIN + k0 + col];
            unsigned d = (unsigned)__cvta_generic_to_shared(&As[b][row * ASTRIDE + col]);
            asm volatile("cp.async.cg.shared.global [%0], [%1], 16, %2;"
                         :: "r"(d), "l"(src), "r"(sz));
        }
#pragma unroll
        for (int i = 0; i < 4; i++) {
            int idx = tid + i * 256;
            int kr = idx >> 5;
            int c4 = (idx & 31) * 4;
            const unsigned* src = &g_wtf[(size_t)(k0 + kr) * FG + c4];
            unsigned d = (unsigned)__cvta_generic_to_shared(&Bs[b][kr * BSTRIDE + c4]);
            asm volatile("cp.async.cg.shared.global [%0], [%1], 16;"
                         :: "r"(d), "l"(src));
        }
        asm volatile("cp.async.commit_group;");
    };

    load_tile(0, 0);
    load_tile(1, 1);

    for (int t = 0; t < TILES; t++) {
        if (t + 1 < TILES) {
            asm volatile("cp.async.wait_group %0;" :: "n"(1));
        } else {
            asm volatile("cp.async.wait_group %0;" :: "n"(0));
        }
        __syncthreads();
        if (t + 2 < TILES) load_tile(t + 2, (t + 2) % STAGES);

        int buf = t % STAGES;
#pragma unroll
        for (int kk = 0; kk < BK; kk += 8) {
            unsigned a[2][4];
#pragma unroll
            for (int m = 0; m < 2; m++) {
                int r0 = warp_m + m * 16 + g;
                a[m][0] = f2tf32(As[buf][(r0    ) * ASTRIDE + kk + tig]);
                a[m][1] = f2tf32(As[buf][(r0 + 8) * ASTRIDE + kk + tig]);
                a[m][2] = f2tf32(As[buf][(r0    ) * ASTRIDE + kk + tig + 4]);
                a[m][3] = f2tf32(As[buf][(r0 + 8) * ASTRIDE + kk + tig + 4]);
            }
            unsigned b[8][2];
#pragma unroll
            for (int n = 0; n < 8; n++) {
                int c0 = warp_n + n * 8 + g;
                b[n][0] = Bs[buf][(kk + tig    ) * BSTRIDE + c0];
                b[n][1] = Bs[buf][(kk + tig + 4) * BSTRIDE + c0];
            }
#pragma unroll
            for (int m = 0; m < 2; m++)
#pragma unroll
                for (int n = 0; n < 8; n++) {
                    asm volatile(
                        "mma.sync.aligned.m16n8k8.row.col.f32.tf32.tf32.f32 "
                        "{%0,%1,%2,%3}, {%4,%5,%6,%7}, {%8,%9}, {%0,%1,%2,%3};"
                        : "+f"(acc[m][n][0]), "+f"(acc[m][n][1]),
                          "+f"(acc[m][n][2]), "+f"(acc[m][n][3])
                        : "r"(a[m][0]), "r"(a[m][1]), "r"(a[m][2]), "r"(a[m][3]),
                          "r"(b[n][0]), "r"(b[n][1]));
                }
        }
    }

    // epilogue: scale by dinv[row], fp16 store
#pragma unroll
    for (int m = 0; m < 2; m++) {
        int r0 = block_row + warp_m + m * 16 + g;
        int r1 = r0 + 8;
        float d0 = (r0 < M) ? g_dinv[r0] : 0.f;
        float d1 = (r1 < M) ? g_dinv[r1] : 0.f;
#pragma unroll
        for (int n = 0; n < 8; n++) {
            int col = warp_n + n * 8 + tig * 2;
            if (r0 < M) {
                __half2 h = __floats2half2_rn(acc[m][n][0] * d0, acc[m][n][1] * d0);
                *(__half2*)&g_xh[(size_t)r0 * FG + col] = h;
            }
            if (r1 < M) {
                __half2 h = __floats2half2_rn(acc[m][n][2] * d1, acc[m][n][3] * d1);
                *(__half2*)&g_xh[(size_t)r1 * FG + col] = h;
            }
        }
    }
}

// ---- fp16 row load: 4 features per lane ----
__device__ __forceinline__ float4 ldrow4(size_t node, int c4) {
    uint2 u = *(const uint2*)&g_xh[node * FG + c4];
    float2 fa = __half22float2(*(__half2*)&u.x);
    float2 fb = __half22float2(*(__half2*)&u.y);
    return make_float4(fa.x, fa.y, fb.x, fb.y);
}

// ---- gather + pooling with register-resident segmented reduction ----
__device__ __forceinline__ void pool_flush(int b, int c4, float4 sum, float4 mx, int nodes) {
    float* ps = &g_psum[b * FG + c4];
    asm volatile("red.global.add.v4.f32 [%0], {%1,%2,%3,%4};"
                 :: "l"(ps), "f"(sum.x), "f"(sum.y), "f"(sum.z), "f"(sum.w) : "memory");
    int* pm = (int*)&g_pmax[b * FG + c4];
    atomicMax(pm + 0, __float_as_int(mx.x));
    atomicMax(pm + 1, __float_as_int(mx.y));
    atomicMax(pm + 2, __float_as_int(mx.z));
    atomicMax(pm + 3, __float_as_int(mx.w));
    if ((threadIdx.x & 31) == 0) atomicAdd(&g_cnt[b], (float)nodes);
}

__global__ void k_gather_pool(const int* __restrict__ batch, const float* __restrict__ bg, int N) {
    int warp = (blockIdx.x * blockDim.x + threadIdx.x) >> 5;
    int lane = threadIdx.x & 31;
    int n0 = warp * NODES_PER_WARP;
    if (n0 >= N) return;
    int n1 = n0 + NODES_PER_WARP; if (n1 > N) n1 = N;
    int c4 = lane * 4;
    float4 bv = *(const float4*)&bg[c4];

    float4 sum = make_float4(0.f, 0.f, 0.f, 0.f);
    float4 mx  = make_float4(0.f, 0.f, 0.f, 0.f);
    int cur_b = batch[n0];
    int nodes = 0;

    for (int n = n0; n < n1; n++) {
        int b = batch[n];
        if (b != cur_b) {
            pool_flush(cur_b, c4, sum, mx, nodes);
            sum = make_float4(0.f, 0.f, 0.f, 0.f);
            mx  = make_float4(0.f, 0.f, 0.f, 0.f);
            cur_b = b; nodes = 0;
        }
        float4 acc = ldrow4((size_t)n, c4);     // self-loop term (pre-scaled)
        int start = g_rowptr[n];
        int cnt   = g_icnt[n];
        int e = 0;
        for (; e + 4 <= cnt; e += 4) {
            int s0 = g_csr[start + e    ];
            int s1 = g_csr[start + e + 1];
            int s2 = g_csr[start + e + 2];
            int s3 = g_csr[start + e + 3];
            float4 v0 = ldrow4((size_t)s0, c4);
            float4 v1 = ldrow4((size_t)s1, c4);
            float4 v2 = ldrow4((size_t)s2, c4);
            float4 v3 = ldrow4((size_t)s3, c4);
            acc.x += v0.x + v1.x + v2.x + v3.x;
            acc.y += v0.y + v1.y + v2.y + v3.y;
            acc.z += v0.z + v1.z + v2.z + v3.z;
            acc.w += v0.w + v1.w + v2.w + v3.w;
        }
        for (; e < cnt; e++) {
            float4 v = ldrow4((size_t)g_csr[start + e], c4);
            acc.x += v.x; acc.y += v.y; acc.z += v.z; acc.w += v.w;
        }
        float di = g_dinv[n];
        float v0 = fmaxf(fmaf(acc.x, di, bv.x), 0.f);
        float v1 = fmaxf(fmaf(acc.y, di, bv.y), 0.f);
        float v2 = fmaxf(fmaf(acc.z, di, bv.z), 0.f);
        float v3 = fmaxf(fmaf(acc.w, di, bv.w), 0.f);
        sum.x += v0; sum.y += v1; sum.z += v2; sum.w += v3;
        mx.x = fmaxf(mx.x, v0); mx.y = fmaxf(mx.y, v1);
        mx.z = fmaxf(mx.z, v2); mx.w = fmaxf(mx.w, v3);
        nodes++;
    }
    pool_flush(cur_b, c4, sum, mx, nodes);
}

// ---------------- head: encoder/decoder MLPs ----------------
__device__ __forceinline__ float eluf(float x)      { return x > 0.f ? x : expm1f(x); }
__device__ __forceinline__ float softplusf(float x) { return x > 20.f ? x : log1pf(expf(x)); }

__global__ void k_head(const float* __restrict__ eps,
                       const float* __restrict__ We1, const float* __restrict__ be1,
                       const float* __restrict__ We2, const float* __restrict__ be2,
                       const float* __restrict__ We3, const float* __restrict__ be3,
                       const float* __restrict__ Wd1, const float* __restrict__ bd1,
                       const float* __restrict__ Wd2, const float* __restrict__ bd2,
                       const float* __restrict__ Wd3, const float* __restrict__ bd3,
                       float* __restrict__ out, int G) {
    __shared__ float gx[2 * FG];
    __shared__ float t1[HID], t2[HID], ml[2 * ZD], zz[ZD], dd1[HID], dd2[HID];
    int g = blockIdx.x;
    int tid = threadIdx.x;

    float cnt = fmaxf(g_cnt[g], 1.0f);
    gx[tid]      = g_psum[g * FG + tid] / cnt;
    gx[FG + tid] = __int_as_float(g_pmax[g * FG + tid]);
    __syncthreads();

    if (tid < HID) {
        float s = be1[tid];
#pragma unroll 8
        for (int i = 0; i < 2 * FG; i++) s = fmaf(gx[i], We1[i * HID + tid], s);
        t1[tid] = eluf(s);
    }
    __syncthreads();
    if (tid < HID) {
        float s = be2[tid];
#pragma unroll 8
        for (int i = 0; i < HID; i++) s = fmaf(t1[i], We2[i * HID + tid], s);
        t2[tid] = tanhf(s);
    }
    __syncthreads();
    {
        float s = be3[tid];
#pragma unroll 8
        for (int i = 0; i < HID; i++) s = fmaf(t2[i], We3[i * 2 * ZD + tid], s);
        ml[tid] = s;
    }
    __syncthreads();
    if (tid < ZD) {
        float mu = ml[tid];
        float sd = 1e-6f + softplusf(ml[ZD + tid]);
        float z = fmaf(eps[g * ZD + tid], sd, mu);
        zz[tid] = z;
        out[g * ZD + tid] = mu;
        out[G * ZD + g * ZD + tid] = sd;
    }
    __syncthreads();
    if (tid < HID) {
        float s = bd1[tid];
#pragma unroll 8
        for (int i = 0; i < ZD; i++) s = fmaf(zz[i], Wd1[i * HID + tid], s);
        dd1[tid] = tanhf(s);
    }
    __syncthreads();
    if (tid < HID) {
        float s = bd2[tid];
#pragma unroll 8
        for (int i = 0; i < HID; i++) s = fmaf(dd1[i], Wd2[i * HID + tid], s);
        dd2[tid] = eluf(s);
    }
    __syncthreads();
    {
        float s = bd3[tid];
#pragma unroll 8
        for (int i = 0; i < HID; i++) s = fmaf(dd2[i], Wd3[i * FG + tid], s);
        float y = 1.0f / (1.0f + expf(-s));
        y = fminf(fmaxf(y, 1e-8f), 1.0f - 1e-8f);
        out[2 * G * ZD + g * FG + tid] = y;
    }
}

// ---------------- launch (single stream, serial) ----------------
extern "C" void kernel_launch(void* const* d_in, const int* in_sizes, int n_in,
                              void* d_out, int out_size) {
    const float* x     = (const float*)d_in[0];
    const int*   ei    = (const int*)  d_in[1];
    const int*   batch = (const int*)  d_in[2];
    const float* eps   = (const float*)d_in[3];
    const float* Wg    = (const float*)d_in[4];
    const float* bg    = (const float*)d_in[5];
    const float* We1 = (const float*)d_in[6],  *be1 = (const float*)d_in[7];
    const float* We2 = (const float*)d_in[8],  *be2 = (const float*)d_in[9];
    const float* We3 = (const float*)d_in[10], *be3 = (const float*)d_in[11];
    const float* Wd1 = (const float*)d_in[12], *bd1 = (const float*)d_in[13];
    const float* Wd2 = (const float*)d_in[14], *bd2 = (const float*)d_in[15];
    const float* Wd3 = (const float*)d_in[16], *bd3 = (const float*)d_in[17];
    float* out = (float*)d_out;

    int N = in_sizes[0] / FIN;       // 100000
    int E = in_sizes[1] / 2;         // 1600000
    int G = in_sizes[3] / ZD;        // 512
    const int* src = ei;
    const int* dst = ei + E;
    int nb = (N + SCAN_BLK - 1) / SCAN_BLK;

    int pre_n = N > GMAX * FG ? N : GMAX * FG;
    k_pre<<<(pre_n + 255) / 256, 256>>>(Wg, N);
    k_deg<<<(E + 255) / 256, 256>>>(dst, E);
    k_scan1<<<nb, SCAN_BLK>>>(N);
    k_scan2<<<1, MAX_NB>>>(nb);
    k_scan3<<<(N + 255) / 256, 256>>>(N);
    k_fill<<<(E + 255) / 256, 256>>>(src, dst, E);
    k_gemm_tf32<<<(N + BM - 1) / BM, 256>>>(x, N);
    {
        int nwarps = (N + NODES_PER_WARP - 1) / NODES_PER_WARP;
        long long nthreads = (long long)nwarps * 32;
        k_gather_pool<<<(int)((nthreads + 255) / 256), 256>>>(batch, bg, N);
    }
    k_head<<<G, 128>>>(eps, We1, be1, We2, be2, We3, be3,
                       Wd1, bd1, Wd2, bd2, Wd3, bd3, out, G);
}

// round 16
// speedup vs baseline: 1.3739x; 1.0132x over previous
#include <cuda_runtime.h>
#include <cuda_fp16.h>
#include <math.h>

#define NN_MAX 100000
#define NE_MAX 1600000
#define FG 128
#define FIN 512
#define GMAX 512
#define ZD 64
#define HID 64
#define SCAN_BLK 512
#define MAX_NB 256
#define NODES_PER_WARP 8

// ---------------- scratch (device globals) ----------------
__device__ __half g_xh [NN_MAX * FG];   // (x @ Wg) * dinv[row], fp16 gather payload
__device__ float g_dinv[NN_MAX];        // 1/sqrt(deg)
__device__ int   g_icnt[NN_MAX];        // in-degree (excl self loop)
__device__ int   g_rowptr[NN_MAX];      // CSR row starts
__device__ int   g_cur [NN_MAX];        // fill cursors
__device__ int   g_csr [NE_MAX];        // src node per CSR slot
__device__ int   g_bsum[MAX_NB];        // scan chunk totals (raw)
__device__ uint2 g_wpk[(FIN / 32) * 4 * 4 * FG];  // W tf32 bits, packed (k, k+4) pairs
__device__ float g_psum[GMAX * FG];     // pool sum
__device__ unsigned g_pmax[GMAX * FG];  // pool max (float bits, vals >= 0)
__device__ float g_cnt [GMAX];          // nodes per graph

__device__ __forceinline__ unsigned f2tf32(float v) {
    unsigned r;
    asm("cvt.rna.tf32.f32 %0, %1;" : "=r"(r) : "f"(v));
    return r;
}

// ---------------- fused pre-kernel: pool init + icnt zero + W tf32 pack ----------------
// g_wpk layout: [tile t][kkg][tig][n] uint2, where pair = (W[t*32+kkg*8+tig][n], W[...+4][n])
__global__ void k_pre(const float* __restrict__ W, int N) {
    int i = blockIdx.x * blockDim.x + threadIdx.x;
    if (i < GMAX * FG) { g_psum[i] = 0.f; g_pmax[i] = 0u; }
    if (i < GMAX) g_cnt[i] = 0.f;
    if (i < N) g_icnt[i] = 0;
    if (i < (FIN / 32) * 4 * 4 * FG) {   // 32768
        int n   = i & 127;
        int tig = (i >> 7) & 3;
        int kkg = (i >> 9) & 3;
        int t   = i >> 11;
        int ka = t * 32 + kkg * 8 + tig;
        uint2 u;
        u.x = f2tf32(W[ka * FG + n]);
        u.y = f2tf32(W[(ka + 4) * FG + n]);
        g_wpk[i] = u;
    }
}

// ---------------- degree histogram ----------------
__global__ void k_deg(const int* __restrict__ dst, int E) {
    int e = blockIdx.x * blockDim.x + threadIdx.x;
    if (e < E) atomicAdd(&g_icnt[dst[e]], 1);
}

// ---------------- per-chunk scan of icnt -> local rowptr + chunk totals ----------------
__global__ void k_scan1(int N) {
    __shared__ int sh[SCAN_BLK];
    int tid = threadIdx.x;
    int i = blockIdx.x * SCAN_BLK + tid;
    int v = (i < N) ? g_icnt[i] : 0;
    sh[tid] = v;
    __syncthreads();
#pragma unroll
    for (int off = 1; off < SCAN_BLK; off <<= 1) {
        int t = (tid >= off) ? sh[tid - off] : 0;
        __syncthreads();
        sh[tid] += t;
        __syncthreads();
    }
    if (i < N) g_rowptr[i] = sh[tid] - v;                  // exclusive within chunk
    if (tid == SCAN_BLK - 1) g_bsum[blockIdx.x] = sh[tid]; // chunk TOTAL (raw)
}

// fused fixup: each block reduces g_bsum[0..chunk) itself; + cursor seed + dinv
__global__ void k_scan3(int N) {
    __shared__ int red[256];
    int tid = threadIdx.x;
    int i = blockIdx.x * 256 + tid;
    int chunk = blockIdx.x >> 1;     // two 256-blocks span one 512-chunk

    red[tid] = (tid < chunk) ? g_bsum[tid] : 0;   // chunk <= 195 < 256
    __syncthreads();
#pragma unroll
    for (int off = 128; off > 0; off >>= 1) {
        if (tid < off) red[tid] += red[tid + off];
        __syncthreads();
    }
    int prefix = red[0];

    if (i < N) {
        int r = g_rowptr[i] + prefix;
        g_rowptr[i] = r;
        g_cur[i] = r;
        g_dinv[i] = rsqrtf((float)(g_icnt[i] + 1));   // +1 self loop
    }
}

// ---------------- CSR fill ----------------
__global__ void k_fill(const int* __restrict__ src, const int* __restrict__ dst, int E) {
    int e = blockIdx.x * blockDim.x + threadIdx.x;
    if (e < E) {
        int pos = atomicAdd(&g_cur[dst[e]], 1);
        g_csr[pos] = src[e];
    }
}

// ---------------- TF32 GEMM: 3-stage cp.async, packed-B LDS.64 fragments ----------------
#define BM 128
#define BN 128
#define BK 32
#define TILES (FIN / BK)
#define STAGES 3
#define ASTRIDE 36        // A frag: bank = 4g + tig -> 32 distinct
#define BPK_STRIDE 132    // uint2 stride; 132 % 16 == 4 -> (4*tig + g) distinct per phase
#define BPK_ROWS 16       // 4 kkg * 4 tig
#define BPK_ELEMS (BPK_ROWS * BPK_STRIDE)   // uint2 per stage (2112)

__global__ __launch_bounds__(256, 2)
void k_gemm_tf32(const float* __restrict__ X, int M) {
    __shared__ float As[STAGES][BM * ASTRIDE];
    __shared__ uint2 Bs[STAGES][BPK_ELEMS];
    int tid = threadIdx.x;
    int lane = tid & 31, wid = tid >> 5;
    int warp_m = (wid & 3) * 32;
    int warp_n = (wid >> 2) * 64;
    int g  = lane >> 2;
    int tig = lane & 3;
    int block_row = blockIdx.x * BM;

    float acc[2][8][4];
#pragma unroll
    for (int m = 0; m < 2; m++)
#pragma unroll
        for (int n = 0; n < 8; n++)
#pragma unroll
            for (int c = 0; c < 4; c++) acc[m][n][c] = 0.f;

    auto load_tile = [&](int t, int b) {
        int k0 = t * BK;
#pragma unroll
        for (int i = 0; i < 4; i++) {
            int idx = tid + i * 256;
            int row = idx >> 3;
            int col = (idx & 7) * 4;
            int grow = block_row + row;
            int cg = grow < M ? grow : 0;
            int sz = grow < M ? 16 : 0;
            const float* src = &X[(size_t)cg * FIN + k0 + col];
            unsigned d = (unsigned)__cvta_generic_to_shared(&As[b][row * ASTRIDE + col]);
            asm volatile("cp.async.cg.shared.global [%0], [%1], 16, %2;"
                         :: "r"(d), "l"(src), "r"(sz));
        }
        // B: 16 rows x 128 uint2 = 1024 x 16B chunks; 4 per thread
#pragma unroll
        for (int i = 0; i < 4; i++) {
            int idx = tid + i * 256;
            int row = idx >> 6;            // 0..15 (kkg*4 + tig)
            int n0  = (idx & 63) * 2;      // 0..126
            const uint2* src = &g_wpk[(size_t)t * (BPK_ROWS * FG) + row * FG + n0];
            unsigned d = (unsigned)__cvta_generic_to_shared(&Bs[b][row * BPK_STRIDE + n0]);
            asm volatile("cp.async.cg.shared.global [%0], [%1], 16;"
                         :: "r"(d), "l"(src));
        }
        asm volatile("cp.async.commit_group;");
    };

    load_tile(0, 0);
    load_tile(1, 1);

    for (int t = 0; t < TILES; t++) {
        if (t + 1 < TILES) {
            asm volatile("cp.async.wait_group %0;" :: "n"(1));
        } else {
            asm volatile("cp.async.wait_group %0;" :: "n"(0));
        }
        __syncthreads();
        if (t + 2 < TILES) load_tile(t + 2, (t + 2) % STAGES);

        int buf = t % STAGES;
#pragma unroll
        for (int kk = 0; kk < BK; kk += 8) {
            int kkg = kk >> 3;
            unsigned a[2][4];
#pragma unroll
            for (int m = 0; m < 2; m++) {
                int r0 = warp_m + m * 16 + g;
                a[m][0] = f2tf32(As[buf][(r0    ) * ASTRIDE + kk + tig]);
                a[m][1] = f2tf32(As[buf][(r0 + 8) * ASTRIDE + kk + tig]);
                a[m][2] = f2tf32(As[buf][(r0    ) * ASTRIDE + kk + tig + 4]);
                a[m][3] = f2tf32(As[buf][(r0 + 8) * ASTRIDE + kk + tig + 4]);
            }
            uint2 b[8];
            int bbase = (kkg * 4 + tig) * BPK_STRIDE + warp_n + g;
#pragma unroll
            for (int n = 0; n < 8; n++)
                b[n] = Bs[buf][bbase + n * 8];
#pragma unroll
            for (int m = 0; m < 2; m++)
#pragma unroll
                for (int n = 0; n < 8; n++) {
                    asm volatile(
                        "mma.sync.aligned.m16n8k8.row.col.f32.tf32.tf32.f32 "
                        "{%0,%1,%2,%3}, {%4,%5,%6,%7}, {%8,%9}, {%0,%1,%2,%3};"
                        : "+f"(acc[m][n][0]), "+f"(acc[m][n][1]),
                          "+f"(acc[m][n][2]), "+f"(acc[m][n][3])
                        : "r"(a[m][0]), "r"(a[m][1]), "r"(a[m][2]), "r"(a[m][3]),
                          "r"(b[n].x), "r"(b[n].y));
                }
        }
    }

    // epilogue: scale by dinv[row], fp16 store
#pragma unroll
    for (int m = 0; m < 2; m++) {
        int r0 = block_row + warp_m + m * 16 + g;
        int r1 = r0 + 8;
        float d0 = (r0 < M) ? g_dinv[r0] : 0.f;
        float d1 = (r1 < M) ? g_dinv[r1] : 0.f;
#pragma unroll
        for (int n = 0; n < 8; n++) {
            int col = warp_n + n * 8 + tig * 2;
            if (r0 < M) {
                __half2 h = __floats2half2_rn(acc[m][n][0] * d0, acc[m][n][1] * d0);
                *(__half2*)&g_xh[(size_t)r0 * FG + col] = h;
            }
            if (r1 < M) {
                __half2 h = __floats2half2_rn(acc[m][n][2] * d1, acc[m][n][3] * d1);
                *(__half2*)&g_xh[(size_t)r1 * FG + col] = h;
            }
        }
    }
}

// ---- fp16 row load: 4 features per lane ----
__device__ __forceinline__ float4 ldrow4(size_t node, int c4) {
    uint2 u = *(const uint2*)&g_xh[node * FG + c4];
    float2 fa = __half22float2(*(__half2*)&u.x);
    float2 fb = __half22float2(*(__half2*)&u.y);
    return make_float4(fa.x, fa.y, fb.x, fb.y);
}

// ---- gather + pooling with register-resident segmented reduction ----
__device__ __forceinline__ void pool_flush(int b, int c4, float4 sum, float4 mx, int nodes) {
    float* ps = &g_psum[b * FG + c4];
    asm volatile("red.global.add.v4.f32 [%0], {%1,%2,%3,%4};"
                 :: "l"(ps), "f"(sum.x), "f"(sum.y), "f"(sum.z), "f"(sum.w) : "memory");
    int* pm = (int*)&g_pmax[b * FG + c4];
    atomicMax(pm + 0, __float_as_int(mx.x));
    atomicMax(pm + 1, __float_as_int(mx.y));
    atomicMax(pm + 2, __float_as_int(mx.z));
    atomicMax(pm + 3, __float_as_int(mx.w));
    if ((threadIdx.x & 31) == 0) atomicAdd(&g_cnt[b], (float)nodes);
}

__global__ void k_gather_pool(const int* __restrict__ batch, const float* __restrict__ bg, int N) {
    int warp = (blockIdx.x * blockDim.x + threadIdx.x) >> 5;
    int lane = threadIdx.x & 31;
    int n0 = warp * NODES_PER_WARP;
    if (n0 >= N) return;
    int n1 = n0 + NODES_PER_WARP; if (n1 > N) n1 = N;
    int c4 = lane * 4;
    float4 bv = *(const float4*)&bg[c4];

    float4 sum = make_float4(0.f, 0.f, 0.f, 0.f);
    float4 mx  = make_float4(0.f, 0.f, 0.f, 0.f);
    int cur_b = batch[n0];
    int nodes = 0;

    for (int n = n0; n < n1; n++) {
        int b = batch[n];
        if (b != cur_b) {
            pool_flush(cur_b, c4, sum, mx, nodes);
            sum = make_float4(0.f, 0.f, 0.f, 0.f);
            mx  = make_float4(0.f, 0.f, 0.f, 0.f);
            cur_b = b; nodes = 0;
        }
        float4 acc = ldrow4((size_t)n, c4);     // self-loop term (pre-scaled)
        int start = g_rowptr[n];
        int cnt   = g_icnt[n];
        int e = 0;
        for (; e + 4 <= cnt; e += 4) {
            int s0 = g_csr[start + e    ];
            int s1 = g_csr[start + e + 1];
            int s2 = g_csr[start + e + 2];
            int s3 = g_csr[start + e + 3];
            float4 v0 = ldrow4((size_t)s0, c4);
            float4 v1 = ldrow4((size_t)s1, c4);
            float4 v2 = ldrow4((size_t)s2, c4);
            float4 v3 = ldrow4((size_t)s3, c4);
            acc.x += v0.x + v1.x + v2.x + v3.x;
            acc.y += v0.y + v1.y + v2.y + v3.y;
            acc.z += v0.z + v1.z + v2.z + v3.z;
            acc.w += v0.w + v1.w + v2.w + v3.w;
        }
        for (; e < cnt; e++) {
            float4 v = ldrow4((size_t)g_csr[start + e], c4);
            acc.x += v.x; acc.y += v.y; acc.z += v.z; acc.w += v.w;
        }
        float di = g_dinv[n];
        float v0 = fmaxf(fmaf(acc.x, di, bv.x), 0.f);
        float v1 = fmaxf(fmaf(acc.y, di, bv.y), 0.f);
        float v2 = fmaxf(fmaf(acc.z, di, bv.z), 0.f);
        float v3 = fmaxf(fmaf(acc.w, di, bv.w), 0.f);
        sum.x += v0; sum.y += v1; sum.z += v2; sum.w += v3;
        mx.x = fmaxf(mx.x, v0); mx.y = fmaxf(mx.y, v1);
        mx.z = fmaxf(mx.z, v2); mx.w = fmaxf(mx.w, v3);
        nodes++;
    }
    pool_flush(cur_b, c4, sum, mx, nodes);
}

// ---------------- head: encoder/decoder MLPs ----------------
__device__ __forceinline__ float eluf(float x)      { return x > 0.f ? x : expm1f(x); }
__device__ __forceinline__ float softplusf(float x) { return x > 20.f ? x : log1pf(expf(x)); }

__global__ void k_head(const float* __restrict__ eps,
                       const float* __restrict__ We1, const float* __restrict__ be1,
                       const float* __restrict__ We2, const float* __restrict__ be2,
                       const float* __restrict__ We3, const float* __restrict__ be3,
                       const float* __restrict__ Wd1, const float* __restrict__ bd1,
                       const float* __restrict__ Wd2, const float* __restrict__ bd2,
                       const float* __restrict__ Wd3, const float* __restrict__ bd3,
                       float* __restrict__ out, int G) {
    __shared__ float gx[2 * FG];
    __shared__ float t1[HID], t2[HID], ml[2 * ZD], zz[ZD], dd1[HID], dd2[HID];
    int g = blockIdx.x;
    int tid = threadIdx.x;

    float cnt = fmaxf(g_cnt[g], 1.0f);
    gx[tid]      = g_psum[g * FG + tid] / cnt;
    gx[FG + tid] = __int_as_float(g_pmax[g * FG + tid]);
    __syncthreads();

    if (tid < HID) {
        float s = be1[tid];
#pragma unroll 8
        for (int i = 0; i < 2 * FG; i++) s = fmaf(gx[i], We1[i * HID + tid], s);
        t1[tid] = eluf(s);
    }
    __syncthreads();
    if (tid < HID) {
        float s = be2[tid];
#pragma unroll 8
        for (int i = 0; i < HID; i++) s = fmaf(t1[i], We2[i * HID + tid], s);
        t2[tid] = tanhf(s);
    }
    __syncthreads();
    {
        float s = be3[tid];
#pragma unroll 8
        for (int i = 0; i < HID; i++) s = fmaf(t2[i], We3[i * 2 * ZD + tid], s);
        ml[tid] = s;
    }
    __syncthreads();
    if (tid < ZD) {
        float mu = ml[tid];
        float sd = 1e-6f + softplusf(ml[ZD + tid]);
        float z = fmaf(eps[g * ZD + tid], sd, mu);
        zz[tid] = z;
        out[g * ZD + tid] = mu;
        out[G * ZD + g * ZD + tid] = sd;
    }
    __syncthreads();
    if (tid < HID) {
        float s = bd1[tid];
#pragma unroll 8
        for (int i = 0; i < ZD; i++) s = fmaf(zz[i], Wd1[i * HID + tid], s);
        dd1[tid] = tanhf(s);
    }
    __syncthreads();
    if (tid < HID) {
        float s = bd2[tid];
#pragma unroll 8
        for (int i = 0; i < HID; i++) s = fmaf(dd1[i], Wd2[i * HID + tid], s);
        dd2[tid] = eluf(s);
    }
    __syncthreads();
    {
        float s = bd3[tid];
#pragma unroll 8
        for (int i = 0; i < HID; i++) s = fmaf(dd2[i], Wd3[i * FG + tid], s);
        float y = 1.0f / (1.0f + expf(-s));
        y = fminf(fmaxf(y, 1e-8f), 1.0f - 1e-8f);
        out[2 * G * ZD + g * FG + tid] = y;
    }
}

// ---------------- launch (single stream, serial) ----------------
extern "C" void kernel_launch(void* const* d_in, const int* in_sizes, int n_in,
                              void* d_out, int out_size) {
    const float* x     = (const float*)d_in[0];
    const int*   ei    = (const int*)  d_in[1];
    const int*   batch = (const int*)  d_in[2];
    const float* eps   = (const float*)d_in[3];
    const float* Wg    = (const float*)d_in[4];
    const float* bg    = (const float*)d_in[5];
    const float* We1 = (const float*)d_in[6],  *be1 = (const float*)d_in[7];
    const float* We2 = (const float*)d_in[8],  *be2 = (const float*)d_in[9];
    const float* We3 = (const float*)d_in[10], *be3 = (const float*)d_in[11];
    const float* Wd1 = (const float*)d_in[12], *bd1 = (const float*)d_in[13];
    const float* Wd2 = (const float*)d_in[14], *bd2 = (const float*)d_in[15];
    const float* Wd3 = (const float*)d_in[16], *bd3 = (const float*)d_in[17];
    float* out = (float*)d_out;

    int N = in_sizes[0] / FIN;       // 100000
    int E = in_sizes[1] / 2;         // 1600000
    int G = in_sizes[3] / ZD;        // 512
    const int* src = ei;
    const int* dst = ei + E;
    int nb = (N + SCAN_BLK - 1) / SCAN_BLK;

    int pre_n = N > GMAX * FG ? N : GMAX * FG;
    k_pre<<<(pre_n + 255) / 256, 256>>>(Wg, N);
    k_deg<<<(E + 255) / 256, 256>>>(dst, E);
    k_scan1<<<nb, SCAN_BLK>>>(N);
    k_scan3<<<(N + 255) / 256, 256>>>(N);   // fused: bsum reduce + fixup + cursor + dinv
    k_fill<<<(E + 255) / 256, 256>>>(src, dst, E);
    k_gemm_tf32<<<(N + BM - 1) / BM, 256>>>(x, N);
    {
        int nwarps = (N + NODES_PER_WARP - 1) / NODES_PER_WARP;
        long long nthreads = (long long)nwarps * 32;
        k_gather_pool<<<(int)((nthreads + 255) / 256), 256>>>(batch, bg, N);
    }
    k_head<<<G, 128>>>(eps, We1, be1, We2, be2, We3, be3,
                       Wd1, bd1, Wd2, bd2, Wd3, bd3, out, G);
}